// round 3
// baseline (speedup 1.0000x reference)
#include <cuda_runtime.h>

#define NN 50000
#define EE 800000
#define DD 64

// ---------------- scratch (device globals; no allocations allowed) ----------
__device__ float g_y[NN * DD];       // y = x @ W_msg + (b_msg + b_edge)
__device__ int   g_counts[NN];
__device__ int   g_offsets[NN];
__device__ int   g_cursor[NN];
__device__ int   g_eids[EE];
__device__ float g_logits[EE];

// ---------------- K0: zero counts -------------------------------------------
__global__ void init_kernel() {
    int i = blockIdx.x * blockDim.x + threadIdx.x;
    if (i < NN) g_counts[i] = 0;
}

// ---------------- K1: y = x @ W + (b_msg + b_edge) ---------------------------
// block = 256 threads, 64 rows per block. W + x-tile in smem.
__global__ void gemm_kernel(const float* __restrict__ x, const float* __restrict__ W,
                            const float* __restrict__ bm, const float* __restrict__ be) {
    __shared__ float sW[64 * 64];
    __shared__ float sx[64 * 65];   // padded: stride 65 avoids 64-way conflicts
    int t = threadIdx.x;
    int r0 = blockIdx.x * 64;

    for (int i = t; i < 4096; i += 256) sW[i] = W[i];
    for (int i = t; i < 4096; i += 256) {
        int r = i >> 6, c = i & 63;
        int gr = r0 + r;
        sx[r * 65 + c] = (gr < NN) ? x[(long)gr * 64 + c] : 0.f;
    }
    __syncthreads();

    int row = t >> 2;
    int cg  = (t & 3) * 16;
    float acc[16];
#pragma unroll
    for (int j = 0; j < 16; j++) acc[j] = 0.f;

#pragma unroll 8
    for (int k = 0; k < 64; k++) {
        float xv = sx[row * 65 + k];
        const float4* wp = (const float4*)(sW + k * 64 + cg);
#pragma unroll
        for (int j4 = 0; j4 < 4; j4++) {
            float4 wv = wp[j4];
            acc[j4 * 4 + 0] += xv * wv.x;
            acc[j4 * 4 + 1] += xv * wv.y;
            acc[j4 * 4 + 2] += xv * wv.z;
            acc[j4 * 4 + 3] += xv * wv.w;
        }
    }

    int gr = r0 + row;
    if (gr < NN) {
#pragma unroll
        for (int j = 0; j < 16; j++) {
            int c = cg + j;
            g_y[(long)gr * 64 + c] = acc[j] + bm[c] + be[c];
        }
    }
}

// ---------------- K2: histogram of dst ---------------------------------------
__global__ void hist_kernel(const int* __restrict__ ei) {
    int e = blockIdx.x * blockDim.x + threadIdx.x;
    if (e < EE) {
        int d = ei[EE + e];
        atomicAdd(&g_counts[d], 1);
    }
}

// ---------------- K3: single-block exclusive scan (warp-scan based) ----------
__global__ void scan_kernel() {
    __shared__ int wsum[32];
    __shared__ int carry_s;
    int t = threadIdx.x, lane = t & 31, w = t >> 5;
    if (t == 0) carry_s = 0;
    __syncthreads();

    for (int base = 0; base < NN; base += 1024) {
        int idx = base + t;
        int v = (idx < NN) ? g_counts[idx] : 0;
        // inclusive warp scan
        int s = v;
#pragma unroll
        for (int d = 1; d < 32; d <<= 1) {
            int u = __shfl_up_sync(0xFFFFFFFFu, s, d);
            if (lane >= d) s += u;
        }
        if (lane == 31) wsum[w] = s;
        __syncthreads();
        if (w == 0) {
            int ws = wsum[lane];
#pragma unroll
            for (int d = 1; d < 32; d <<= 1) {
                int u = __shfl_up_sync(0xFFFFFFFFu, ws, d);
                if (lane >= d) ws += u;
            }
            wsum[lane] = ws;
        }
        __syncthreads();
        int excl = carry_s + (w > 0 ? wsum[w - 1] : 0) + s - v;
        if (idx < NN) { g_offsets[idx] = excl; g_cursor[idx] = excl; }
        __syncthreads();
        if (t == 0) carry_s += wsum[31];
        __syncthreads();
    }
}

// ---------------- K4: scatter edge ids into CSR ------------------------------
__global__ void scatter_kernel(const int* __restrict__ ei) {
    int e = blockIdx.x * blockDim.x + threadIdx.x;
    if (e < EE) {
        int d = ei[EE + e];
        int p = atomicAdd(&g_cursor[d], 1);
        g_eids[p] = e;
    }
}

// ---------------- K5: per-edge attention logits (warp per edge) ---------------
__global__ void logits_kernel(const int* __restrict__ ei, const float* __restrict__ ea,
                              const float* __restrict__ We, const float* __restrict__ att) {
    int gid = blockIdx.x * blockDim.x + threadIdx.x;
    int e = gid >> 5, lane = gid & 31;
    if (e >= EE) return;

    int   s = __ldg(ei + e);
    float a = __ldg(ea + e);

    float2 yv = *(const float2*)(g_y + ((long)s << 6) + (lane << 1));
    float2 we = *(const float2*)(We + (lane << 1));
    float2 at = *(const float2*)(att + (lane << 1));

    float m0 = yv.x + a * we.x;
    float m1 = yv.y + a * we.y;
    // leaky_relu(v, 0.2) == max(v, 0.2v)
    float p = fmaxf(m0, 0.2f * m0) * at.x + fmaxf(m1, 0.2f * m1) * at.y;
#pragma unroll
    for (int d = 16; d; d >>= 1) p += __shfl_xor_sync(0xFFFFFFFFu, p, d);
    if (lane == 0) g_logits[e] = p;
}

// ---------------- K6: per-node softmax + weighted segment-max + residual -----
__global__ void agg_kernel(const int* __restrict__ ei, const float* __restrict__ ea,
                           const float* __restrict__ x, const float* __restrict__ We,
                           float* __restrict__ out) {
    int gid = blockIdx.x * blockDim.x + threadIdx.x;
    int n = gid >> 5, lane = gid & 31;
    if (n >= NN) return;

    int off = g_offsets[n];
    int k   = g_counts[n];
    int c0  = lane << 1;

    float2 xv = *(const float2*)(x + ((long)n << 6) + c0);
    float o0 = xv.x, o1 = xv.y;

    if (k > 0) {
        // pass 1: online softmax stats over this segment's logits
        const float BIG = -1e30f;
        float mloc = BIG, sloc = 0.f;
        for (int i = lane; i < k; i += 32) {
            float l = g_logits[g_eids[off + i]];
            float nm = fmaxf(mloc, l);
            sloc = sloc * __expf(mloc - nm) + __expf(l - nm);
            mloc = nm;
        }
#pragma unroll
        for (int d = 16; d; d >>= 1) {
            float mo = __shfl_xor_sync(0xFFFFFFFFu, mloc, d);
            float so = __shfl_xor_sync(0xFFFFFFFFu, sloc, d);
            float mn = fmaxf(mloc, mo);
            sloc = sloc * __expf(mloc - mn) + so * __expf(mo - mn);
            mloc = mn;
        }
        float rden = 1.f / (sloc + 1e-16f);
        float m = mloc;

        float2 we = *(const float2*)(We + c0);
        float a0 = BIG, a1 = BIG;
        for (int j = 0; j < k; j++) {
            int   e = g_eids[off + j];             // warp-uniform broadcast
            float l = g_logits[e];
            float alpha = __expf(l - m) * rden;
            int   s = ei[e];
            float av = ea[e];
            float2 yv = *(const float2*)(g_y + ((long)s << 6) + c0);
            a0 = fmaxf(a0, (yv.x + av * we.x) * alpha);
            a1 = fmaxf(a1, (yv.y + av * we.y) * alpha);
        }
        o0 += a0;
        o1 += a1;
    }
    *(float2*)(out + ((long)n << 6) + c0) = make_float2(o0, o1);
}

// ---------------- launch ------------------------------------------------------
extern "C" void kernel_launch(void* const* d_in, const int* in_sizes, int n_in,
                              void* d_out, int out_size) {
    const float* x   = (const float*)d_in[0];
    const int*   ei  = (const int*)d_in[1];
    const float* ea  = (const float*)d_in[2];
    const float* Wm  = (const float*)d_in[3];
    const float* bm  = (const float*)d_in[4];
    const float* We  = (const float*)d_in[5];
    const float* be  = (const float*)d_in[6];
    const float* att = (const float*)d_in[7];
    float*       out = (float*)d_out;
    (void)in_sizes; (void)n_in; (void)out_size;

    init_kernel<<<(NN + 255) / 256, 256>>>();
    gemm_kernel<<<(NN + 63) / 64, 256>>>(x, Wm, bm, be);
    hist_kernel<<<(EE + 255) / 256, 256>>>(ei);
    scan_kernel<<<1, 1024>>>();
    scatter_kernel<<<(EE + 255) / 256, 256>>>(ei);
    logits_kernel<<<(EE * 32) / 256, 256>>>(ei, ea, We, att);
    agg_kernel<<<(NN * 32 + 255) / 256, 256>>>(ei, ea, x, We, out);
}

// round 5
// speedup vs baseline: 1.1409x; 1.1409x over previous
#include <cuda_runtime.h>

#define NN 50000
#define EE 800000
#define DD 64
#define SCAN_BS 512
#define SCAN_NB ((NN + SCAN_BS - 1) / SCAN_BS)   // 98

// ---------------- scratch (device globals; no allocations allowed) ----------
__device__ float g_y[NN * DD];        // y = x @ W_msg + (b_msg + b_edge)
__device__ int   g_counts[NN];
__device__ int   g_offsets[NN];
__device__ int   g_cursor[NN];
__device__ int   g_part[SCAN_NB];
__device__ int   g_src_csr[EE];       // per-CSR-slot: src node
__device__ float g_ea_csr[EE];        // per-CSR-slot: edge_attr
__device__ float g_logit_csr[EE];     // per-CSR-slot: attention logit

// ---------------- K0: zero counts -------------------------------------------
__global__ void init_kernel() {
    int i = blockIdx.x * blockDim.x + threadIdx.x;
    if (i < NN) g_counts[i] = 0;
}

// ---------------- K1: y = x @ W + (b_msg + b_edge) ---------------------------
__global__ void gemm_kernel(const float* __restrict__ x, const float* __restrict__ W,
                            const float* __restrict__ bm, const float* __restrict__ be) {
    __shared__ float sW[64 * 64];
    __shared__ float sx[64 * 65];
    int t = threadIdx.x;
    int r0 = blockIdx.x * 64;

    for (int i = t; i < 4096; i += 256) sW[i] = W[i];
    for (int i = t; i < 4096; i += 256) {
        int r = i >> 6, c = i & 63;
        int gr = r0 + r;
        sx[r * 65 + c] = (gr < NN) ? x[(long)gr * 64 + c] : 0.f;
    }
    __syncthreads();

    int row = t >> 2;
    int cg  = (t & 3) * 16;
    float acc[16];
#pragma unroll
    for (int j = 0; j < 16; j++) acc[j] = 0.f;

#pragma unroll 8
    for (int k = 0; k < 64; k++) {
        float xv = sx[row * 65 + k];
        const float4* wp = (const float4*)(sW + k * 64 + cg);
#pragma unroll
        for (int j4 = 0; j4 < 4; j4++) {
            float4 wv = wp[j4];
            acc[j4 * 4 + 0] += xv * wv.x;
            acc[j4 * 4 + 1] += xv * wv.y;
            acc[j4 * 4 + 2] += xv * wv.z;
            acc[j4 * 4 + 3] += xv * wv.w;
        }
    }

    int gr = r0 + row;
    if (gr < NN) {
#pragma unroll
        for (int j = 0; j < 16; j++) {
            int c = cg + j;
            g_y[(long)gr * 64 + c] = acc[j] + bm[c] + be[c];
        }
    }
}

// ---------------- K2: histogram of dst ---------------------------------------
__global__ void hist_kernel(const int* __restrict__ ei) {
    int e = blockIdx.x * blockDim.x + threadIdx.x;
    if (e < EE) atomicAdd(&g_counts[ei[EE + e]], 1);
}

// ---------------- K3a: per-block exclusive scan ------------------------------
__global__ void scan_blocks_kernel() {
    __shared__ int wsum[16];
    int t = threadIdx.x, lane = t & 31, w = t >> 5;
    int idx = blockIdx.x * SCAN_BS + t;
    int v = (idx < NN) ? g_counts[idx] : 0;
    int s = v;
#pragma unroll
    for (int d = 1; d < 32; d <<= 1) {
        int u = __shfl_up_sync(0xFFFFFFFFu, s, d);
        if (lane >= d) s += u;
    }
    if (lane == 31) wsum[w] = s;
    __syncthreads();
    if (w == 0) {                         // ALL 32 lanes participate in shfl
        int ws = (lane < 16) ? wsum[lane] : 0;
#pragma unroll
        for (int d = 1; d < 16; d <<= 1) {
            int u = __shfl_up_sync(0xFFFFFFFFu, ws, d);
            if (lane >= d) ws += u;
        }
        if (lane < 16) wsum[lane] = ws;
    }
    __syncthreads();
    int excl = (w > 0 ? wsum[w - 1] : 0) + s - v;
    if (idx < NN) g_offsets[idx] = excl;
    if (t == SCAN_BS - 1) g_part[blockIdx.x] = wsum[15];
}

// ---------------- K3b: scan the 98 block totals (1 small block) --------------
__global__ void scan_part_kernel() {
    __shared__ int wsum[4];
    int t = threadIdx.x, lane = t & 31, w = t >> 5;   // 128 threads
    int v = (t < SCAN_NB) ? g_part[t] : 0;
    int s = v;
#pragma unroll
    for (int d = 1; d < 32; d <<= 1) {
        int u = __shfl_up_sync(0xFFFFFFFFu, s, d);
        if (lane >= d) s += u;
    }
    if (lane == 31) wsum[w] = s;
    __syncthreads();
    if (t == 0) {
        int c = 0;
#pragma unroll
        for (int i = 0; i < 4; i++) { int tmp = wsum[i]; wsum[i] = c; c += tmp; }
    }
    __syncthreads();
    if (t < SCAN_NB) g_part[t] = wsum[w] + s - v;
}

// ---------------- K3c: add block prefixes ------------------------------------
__global__ void scan_add_kernel() {
    int i = blockIdx.x * blockDim.x + threadIdx.x;
    if (i < NN) {
        int o = g_offsets[i] + g_part[i / SCAN_BS];
        g_offsets[i] = o;
        g_cursor[i]  = o;
    }
}

// ---------------- K4: scatter edges into CSR order ---------------------------
__global__ void scatter_kernel(const int* __restrict__ ei, const float* __restrict__ ea) {
    int e = blockIdx.x * blockDim.x + threadIdx.x;
    if (e < EE) {
        int d = ei[EE + e];
        int p = atomicAdd(&g_cursor[d], 1);
        g_src_csr[p] = ei[e];
        g_ea_csr[p]  = ea[e];
    }
}

// ---------------- K5: logits in CSR order (warp per slot) ---------------------
__global__ void logits_kernel(const float* __restrict__ We, const float* __restrict__ att) {
    int gid = blockIdx.x * blockDim.x + threadIdx.x;
    int p = gid >> 5, lane = gid & 31;
    if (p >= EE) return;

    int   s = g_src_csr[p];
    float a = g_ea_csr[p];

    float2 yv = *(const float2*)(g_y + ((long)s << 6) + (lane << 1));
    float2 we = *(const float2*)(We + (lane << 1));
    float2 at = *(const float2*)(att + (lane << 1));

    float m0 = yv.x + a * we.x;
    float m1 = yv.y + a * we.y;
    float v  = fmaxf(m0, 0.2f * m0) * at.x + fmaxf(m1, 0.2f * m1) * at.y;
#pragma unroll
    for (int d = 16; d; d >>= 1) v += __shfl_xor_sync(0xFFFFFFFFu, v, d);
    if (lane == 0) g_logit_csr[p] = v;
}

// ---------------- K6: per-node softmax + weighted segment-max + residual -----
__global__ void agg_kernel(const float* __restrict__ x, const float* __restrict__ We,
                           float* __restrict__ out) {
    int gid = blockIdx.x * blockDim.x + threadIdx.x;
    int n = gid >> 5, lane = gid & 31;
    if (n >= NN) return;

    int off = g_offsets[n];
    int k   = g_counts[n];
    int c0  = lane << 1;

    float2 xv = *(const float2*)(x + ((long)n << 6) + c0);
    float o0 = xv.x, o1 = xv.y;

    if (k > 0) {
        // pass 1: online softmax stats over contiguous logits
        const float BIG = -1e30f;
        float mloc = BIG, sloc = 0.f;
        for (int i = lane; i < k; i += 32) {
            float l = g_logit_csr[off + i];
            float nm = fmaxf(mloc, l);
            sloc = sloc * __expf(mloc - nm) + __expf(l - nm);
            mloc = nm;
        }
#pragma unroll
        for (int d = 16; d; d >>= 1) {
            float mo = __shfl_xor_sync(0xFFFFFFFFu, mloc, d);
            float so = __shfl_xor_sync(0xFFFFFFFFu, sloc, d);
            float mn = fmaxf(mloc, mo);
            sloc = sloc * __expf(mloc - mn) + so * __expf(mo - mn);
            mloc = mn;
        }
        float rden = 1.f / (sloc + 1e-16f);
        float m = mloc;

        float2 we = *(const float2*)(We + c0);
        float a0 = BIG, a1 = BIG;
#pragma unroll 2
        for (int j = 0; j < k; j++) {
            int   s  = g_src_csr[off + j];         // sequential, warp-uniform
            float l  = g_logit_csr[off + j];
            float av = g_ea_csr[off + j];
            float alpha = __expf(l - m) * rden;
            float2 yv = *(const float2*)(g_y + ((long)s << 6) + c0);
            a0 = fmaxf(a0, (yv.x + av * we.x) * alpha);
            a1 = fmaxf(a1, (yv.y + av * we.y) * alpha);
        }
        o0 += a0;
        o1 += a1;
    }
    *(float2*)(out + ((long)n << 6) + c0) = make_float2(o0, o1);
}

// ---------------- launch ------------------------------------------------------
extern "C" void kernel_launch(void* const* d_in, const int* in_sizes, int n_in,
                              void* d_out, int out_size) {
    const float* x   = (const float*)d_in[0];
    const int*   ei  = (const int*)d_in[1];
    const float* ea  = (const float*)d_in[2];
    const float* Wm  = (const float*)d_in[3];
    const float* bm  = (const float*)d_in[4];
    const float* We  = (const float*)d_in[5];
    const float* be  = (const float*)d_in[6];
    const float* att = (const float*)d_in[7];
    float*       out = (float*)d_out;
    (void)in_sizes; (void)n_in; (void)out_size;

    init_kernel<<<(NN + 255) / 256, 256>>>();
    gemm_kernel<<<(NN + 63) / 64, 256>>>(x, Wm, bm, be);
    hist_kernel<<<(EE + 255) / 256, 256>>>(ei);
    scan_blocks_kernel<<<SCAN_NB, SCAN_BS>>>();
    scan_part_kernel<<<1, 128>>>();
    scan_add_kernel<<<(NN + 255) / 256, 256>>>();
    scatter_kernel<<<(EE + 255) / 256, 256>>>(ei, ea);
    logits_kernel<<<(EE * 32) / 256, 256>>>(We, att);
    agg_kernel<<<(NN * 32 + 255) / 256, 256>>>(x, We, out);
}

// round 7
// speedup vs baseline: 2.0813x; 1.8242x over previous
#include <cuda_runtime.h>

#define NN 50000
#define EE 800000
#define SCAN_BS 512
#define SCAN_NB ((NN + SCAN_BS - 1) / SCAN_BS)   // 98

// ---------------- scratch (device globals; no allocations allowed) ----------
__device__ float g_y[NN * 64];        // y = x @ W_msg + (b_msg + b_edge)
__device__ int   g_counts[NN];
__device__ int   g_offsets[NN];
__device__ int   g_cursor[NN];
__device__ int   g_part[SCAN_NB];
__device__ int2  g_sa_csr[EE];        // per-CSR-slot: {src, edge_attr bits}
__device__ float g_logit_csr[EE];     // per-CSR-slot: attention logit

// ---------------- K1: y = x @ W + (b_msg + b_edge); also zeros counts --------
// 128 threads/block, 128 rows/block, 4 rows x 16 cols per thread.
__global__ void gemm_kernel(const float* __restrict__ x, const float* __restrict__ W,
                            const float* __restrict__ bm, const float* __restrict__ be) {
    __shared__ float sW[4096];
    __shared__ float sx[128 * 65];
    int t  = threadIdx.x;
    int r0 = blockIdx.x * 128;

    int gid = r0 + t;                       // folded init: zero dst counters
    if (gid < NN) g_counts[gid] = 0;

    for (int i = t; i < 1024; i += 128)
        ((float4*)sW)[i] = ((const float4*)W)[i];
    for (int i = t; i < 2048; i += 128) {
        int r = i >> 4, c4 = (i & 15) << 2;
        int gr = r0 + r;
        float4 v = (gr < NN) ? ((const float4*)x)[(gr << 4) + (c4 >> 2)]
                             : make_float4(0.f, 0.f, 0.f, 0.f);
        float* dst = sx + r * 65 + c4;
        dst[0] = v.x; dst[1] = v.y; dst[2] = v.z; dst[3] = v.w;
    }
    __syncthreads();

    int q  = t >> 2;            // row quad 0..31
    int cg = (t & 3) << 4;      // col group 0/16/32/48
    float acc[4][16];
#pragma unroll
    for (int i = 0; i < 4; i++)
#pragma unroll
        for (int j = 0; j < 16; j++) acc[i][j] = 0.f;

#pragma unroll 4
    for (int k = 0; k < 64; k++) {
        const float* wr = sW + (k << 6) + cg;
        float4 w0 = *(const float4*)(wr);
        float4 w1 = *(const float4*)(wr + 4);
        float4 w2 = *(const float4*)(wr + 8);
        float4 w3 = *(const float4*)(wr + 12);
        float wv[16] = {w0.x,w0.y,w0.z,w0.w, w1.x,w1.y,w1.z,w1.w,
                        w2.x,w2.y,w2.z,w2.w, w3.x,w3.y,w3.z,w3.w};
#pragma unroll
        for (int i = 0; i < 4; i++) {
            float xv = sx[(q * 4 + i) * 65 + k];
#pragma unroll
            for (int j = 0; j < 16; j++) acc[i][j] += xv * wv[j];
        }
    }

    float bsum[16];
#pragma unroll
    for (int j = 0; j < 16; j++) bsum[j] = bm[cg + j] + be[cg + j];

#pragma unroll
    for (int i = 0; i < 4; i++) {
        int gr = r0 + q * 4 + i;
        if (gr < NN) {
            float* yo = g_y + ((long)gr << 6) + cg;
#pragma unroll
            for (int j4 = 0; j4 < 4; j4++) {
                float4 v = make_float4(acc[i][j4*4+0] + bsum[j4*4+0],
                                       acc[i][j4*4+1] + bsum[j4*4+1],
                                       acc[i][j4*4+2] + bsum[j4*4+2],
                                       acc[i][j4*4+3] + bsum[j4*4+3]);
                *(float4*)(yo + j4 * 4) = v;
            }
        }
    }
}

// ---------------- K2: histogram of dst ---------------------------------------
__global__ void hist_kernel(const int* __restrict__ ei) {
    int e = blockIdx.x * blockDim.x + threadIdx.x;
    if (e < EE) atomicAdd(&g_counts[ei[EE + e]], 1);
}

// ---------------- K3a: per-block exclusive scan ------------------------------
__global__ void scan_blocks_kernel() {
    __shared__ int wsum[16];
    int t = threadIdx.x, lane = t & 31, w = t >> 5;
    int idx = blockIdx.x * SCAN_BS + t;
    int v = (idx < NN) ? g_counts[idx] : 0;
    int s = v;
#pragma unroll
    for (int d = 1; d < 32; d <<= 1) {
        int u = __shfl_up_sync(0xFFFFFFFFu, s, d);
        if (lane >= d) s += u;
    }
    if (lane == 31) wsum[w] = s;
    __syncthreads();
    if (w == 0) {                         // ALL 32 lanes participate in shfl
        int ws = (lane < 16) ? wsum[lane] : 0;
#pragma unroll
        for (int d = 1; d < 16; d <<= 1) {
            int u = __shfl_up_sync(0xFFFFFFFFu, ws, d);
            if (lane >= d) ws += u;
        }
        if (lane < 16) wsum[lane] = ws;
    }
    __syncthreads();
    int excl = (w > 0 ? wsum[w - 1] : 0) + s - v;
    if (idx < NN) g_offsets[idx] = excl;
    if (t == SCAN_BS - 1) g_part[blockIdx.x] = wsum[15];
}

// ---------------- K3b: scan the 98 block totals ------------------------------
__global__ void scan_part_kernel() {
    __shared__ int wsum[4];
    int t = threadIdx.x, lane = t & 31, w = t >> 5;   // 128 threads
    int v = (t < SCAN_NB) ? g_part[t] : 0;
    int s = v;
#pragma unroll
    for (int d = 1; d < 32; d <<= 1) {
        int u = __shfl_up_sync(0xFFFFFFFFu, s, d);
        if (lane >= d) s += u;
    }
    if (lane == 31) wsum[w] = s;
    __syncthreads();
    if (t == 0) {
        int c = 0;
#pragma unroll
        for (int i = 0; i < 4; i++) { int tmp = wsum[i]; wsum[i] = c; c += tmp; }
    }
    __syncthreads();
    if (t < SCAN_NB) g_part[t] = wsum[w] + s - v;
}

// ---------------- K3c: add block prefixes ------------------------------------
__global__ void scan_add_kernel() {
    int i = blockIdx.x * blockDim.x + threadIdx.x;
    if (i < NN) {
        int o = g_offsets[i] + g_part[i / SCAN_BS];
        g_offsets[i] = o;
        g_cursor[i]  = o;
    }
}

// ---------------- K4: scatter edges into CSR order (one 8B store) ------------
__global__ void scatter_kernel(const int* __restrict__ ei, const float* __restrict__ ea) {
    int e = blockIdx.x * blockDim.x + threadIdx.x;
    if (e < EE) {
        int d = ei[EE + e];
        int p = atomicAdd(&g_cursor[d], 1);
        g_sa_csr[p] = make_int2(ei[e], __float_as_int(ea[e]));
    }
}

// ---------------- K5: logits, 8 lanes/edge, 4 edges/warp ----------------------
__global__ void logits_kernel(const float* __restrict__ We, const float* __restrict__ att) {
    int tid = blockIdx.x * blockDim.x + threadIdx.x;
    int p = tid >> 3;
    if (p >= EE) return;
    int r = tid & 7;

    int2  sa = g_sa_csr[p];
    float a  = __int_as_float(sa.y);
    const float4* yr = (const float4*)(g_y + ((long)sa.x << 6));
    float4 y0 = yr[r];
    float4 y1 = yr[8 + r];
    float4 we0 = ((const float4*)We)[r],  we1 = ((const float4*)We)[8 + r];
    float4 at0 = ((const float4*)att)[r], at1 = ((const float4*)att)[8 + r];

    float m, v = 0.f;
    m = y0.x + a * we0.x; v += fmaxf(m, 0.2f * m) * at0.x;
    m = y0.y + a * we0.y; v += fmaxf(m, 0.2f * m) * at0.y;
    m = y0.z + a * we0.z; v += fmaxf(m, 0.2f * m) * at0.z;
    m = y0.w + a * we0.w; v += fmaxf(m, 0.2f * m) * at0.w;
    m = y1.x + a * we1.x; v += fmaxf(m, 0.2f * m) * at1.x;
    m = y1.y + a * we1.y; v += fmaxf(m, 0.2f * m) * at1.y;
    m = y1.z + a * we1.z; v += fmaxf(m, 0.2f * m) * at1.z;
    m = y1.w + a * we1.w; v += fmaxf(m, 0.2f * m) * at1.w;

    v += __shfl_xor_sync(0xFFFFFFFFu, v, 4);
    v += __shfl_xor_sync(0xFFFFFFFFu, v, 2);
    v += __shfl_xor_sync(0xFFFFFFFFu, v, 1);
    if (r == 0) g_logit_csr[p] = v;
}

// ---------------- K6: per-node softmax + weighted segment-max + residual -----
__global__ void agg_kernel(const float* __restrict__ x, const float* __restrict__ We,
                           float* __restrict__ out) {
    int gid = blockIdx.x * blockDim.x + threadIdx.x;
    int n = gid >> 5, lane = gid & 31;
    if (n >= NN) return;

    int off = g_offsets[n];
    int k   = g_counts[n];
    int c0  = lane << 1;

    float2 xv = *(const float2*)(x + ((long)n << 6) + c0);
    float o0 = xv.x, o1 = xv.y;

    if (k > 0) {
        const float BIG = -1e30f;
        float mloc = BIG, sloc = 0.f;
        for (int i = lane; i < k; i += 32) {
            float l = g_logit_csr[off + i];
            float nm = fmaxf(mloc, l);
            sloc = sloc * __expf(mloc - nm) + __expf(l - nm);
            mloc = nm;
        }
#pragma unroll
        for (int d = 16; d; d >>= 1) {
            float mo = __shfl_xor_sync(0xFFFFFFFFu, mloc, d);
            float so = __shfl_xor_sync(0xFFFFFFFFu, sloc, d);
            float mn = fmaxf(mloc, mo);
            sloc = sloc * __expf(mloc - mn) + so * __expf(mo - mn);
            mloc = mn;
        }
        float rden = 1.f / (sloc + 1e-16f);
        float m = mloc;

        float2 we = *(const float2*)(We + c0);
        float a0 = BIG, a1 = BIG;
        int j = 0;
        for (; j + 4 <= k; j += 4) {
            int2  s0 = g_sa_csr[off + j + 0];
            int2  s1 = g_sa_csr[off + j + 1];
            int2  s2 = g_sa_csr[off + j + 2];
            int2  s3 = g_sa_csr[off + j + 3];
            float l0 = g_logit_csr[off + j + 0];
            float l1 = g_logit_csr[off + j + 1];
            float l2 = g_logit_csr[off + j + 2];
            float l3 = g_logit_csr[off + j + 3];
            float2 y0 = *(const float2*)(g_y + ((long)s0.x << 6) + c0);
            float2 y1 = *(const float2*)(g_y + ((long)s1.x << 6) + c0);
            float2 y2 = *(const float2*)(g_y + ((long)s2.x << 6) + c0);
            float2 y3 = *(const float2*)(g_y + ((long)s3.x << 6) + c0);
            float al0 = __expf(l0 - m) * rden, av0 = __int_as_float(s0.y);
            float al1 = __expf(l1 - m) * rden, av1 = __int_as_float(s1.y);
            float al2 = __expf(l2 - m) * rden, av2 = __int_as_float(s2.y);
            float al3 = __expf(l3 - m) * rden, av3 = __int_as_float(s3.y);
            a0 = fmaxf(a0, (y0.x + av0 * we.x) * al0);
            a1 = fmaxf(a1, (y0.y + av0 * we.y) * al0);
            a0 = fmaxf(a0, (y1.x + av1 * we.x) * al1);
            a1 = fmaxf(a1, (y1.y + av1 * we.y) * al1);
            a0 = fmaxf(a0, (y2.x + av2 * we.x) * al2);
            a1 = fmaxf(a1, (y2.y + av2 * we.y) * al2);
            a0 = fmaxf(a0, (y3.x + av3 * we.x) * al3);
            a1 = fmaxf(a1, (y3.y + av3 * we.y) * al3);
        }
        for (; j < k; j++) {
            int2  s  = g_sa_csr[off + j];
            float l  = g_logit_csr[off + j];
            float av = __int_as_float(s.y);
            float alpha = __expf(l - m) * rden;
            float2 yv = *(const float2*)(g_y + ((long)s.x << 6) + c0);
            a0 = fmaxf(a0, (yv.x + av * we.x) * alpha);
            a1 = fmaxf(a1, (yv.y + av * we.y) * alpha);
        }
        o0 += a0;
        o1 += a1;
    }
    *(float2*)(out + ((long)n << 6) + c0) = make_float2(o0, o1);
}

// ---------------- launch ------------------------------------------------------
extern "C" void kernel_launch(void* const* d_in, const int* in_sizes, int n_in,
                              void* d_out, int out_size) {
    const float* x   = (const float*)d_in[0];
    const int*   ei  = (const int*)d_in[1];
    const float* ea  = (const float*)d_in[2];
    const float* Wm  = (const float*)d_in[3];
    const float* bm  = (const float*)d_in[4];
    const float* We  = (const float*)d_in[5];
    const float* be  = (const float*)d_in[6];
    const float* att = (const float*)d_in[7];
    float*       out = (float*)d_out;
    (void)in_sizes; (void)n_in; (void)out_size;

    gemm_kernel<<<(NN + 127) / 128, 128>>>(x, Wm, bm, be);   // also zeros counts
    hist_kernel<<<(EE + 255) / 256, 256>>>(ei);
    scan_blocks_kernel<<<SCAN_NB, SCAN_BS>>>();
    scan_part_kernel<<<1, 128>>>();
    scan_add_kernel<<<(NN + 255) / 256, 256>>>();
    scatter_kernel<<<(EE + 255) / 256, 256>>>(ei, ea);
    logits_kernel<<<(EE * 8) / 256, 256>>>(We, att);
    agg_kernel<<<(NN * 32) / 256, 256>>>(x, We, out);
}

// round 8
// speedup vs baseline: 2.0943x; 1.0062x over previous
#include <cuda_runtime.h>

#define NN 50000
#define EE 800000
#define SCAN_BS 512
#define SCAN_NB ((NN + SCAN_BS - 1) / SCAN_BS)   // 98
#define CAP 128                                   // per-warp logit cache slots

// ---------------- scratch (device globals; no allocations allowed) ----------
__device__ float g_y[NN * 64];        // y = x @ W_msg + (b_msg + b_edge)
__device__ int   g_counts[NN];
__device__ int   g_offsets[NN];
__device__ int   g_cursor[NN];
__device__ int   g_part[SCAN_NB];
__device__ int2  g_sa_csr[EE];        // per-CSR-slot: {src, edge_attr bits}
__device__ float g_logit_ovf[EE];     // overflow logits (k > CAP only)

// ---------------- K1: y = x @ W + (b_msg + b_edge); also zeros counts --------
__global__ void gemm_kernel(const float* __restrict__ x, const float* __restrict__ W,
                            const float* __restrict__ bm, const float* __restrict__ be) {
    __shared__ float sW[4096];
    __shared__ float sx[128 * 65];
    int t  = threadIdx.x;
    int r0 = blockIdx.x * 128;

    int gid = r0 + t;                       // folded init: zero dst counters
    if (gid < NN) g_counts[gid] = 0;

    for (int i = t; i < 1024; i += 128)
        ((float4*)sW)[i] = ((const float4*)W)[i];
    for (int i = t; i < 2048; i += 128) {
        int r = i >> 4, c4 = (i & 15) << 2;
        int gr = r0 + r;
        float4 v = (gr < NN) ? ((const float4*)x)[(gr << 4) + (c4 >> 2)]
                             : make_float4(0.f, 0.f, 0.f, 0.f);
        float* dst = sx + r * 65 + c4;
        dst[0] = v.x; dst[1] = v.y; dst[2] = v.z; dst[3] = v.w;
    }
    __syncthreads();

    int q  = t >> 2;
    int cg = (t & 3) << 4;
    float acc[4][16];
#pragma unroll
    for (int i = 0; i < 4; i++)
#pragma unroll
        for (int j = 0; j < 16; j++) acc[i][j] = 0.f;

#pragma unroll 4
    for (int k = 0; k < 64; k++) {
        const float* wr = sW + (k << 6) + cg;
        float4 w0 = *(const float4*)(wr);
        float4 w1 = *(const float4*)(wr + 4);
        float4 w2 = *(const float4*)(wr + 8);
        float4 w3 = *(const float4*)(wr + 12);
        float wv[16] = {w0.x,w0.y,w0.z,w0.w, w1.x,w1.y,w1.z,w1.w,
                        w2.x,w2.y,w2.z,w2.w, w3.x,w3.y,w3.z,w3.w};
#pragma unroll
        for (int i = 0; i < 4; i++) {
            float xv = sx[(q * 4 + i) * 65 + k];
#pragma unroll
            for (int j = 0; j < 16; j++) acc[i][j] += xv * wv[j];
        }
    }

    float bsum[16];
#pragma unroll
    for (int j = 0; j < 16; j++) bsum[j] = bm[cg + j] + be[cg + j];

#pragma unroll
    for (int i = 0; i < 4; i++) {
        int gr = r0 + q * 4 + i;
        if (gr < NN) {
            float* yo = g_y + ((long)gr << 6) + cg;
#pragma unroll
            for (int j4 = 0; j4 < 4; j4++) {
                float4 v = make_float4(acc[i][j4*4+0] + bsum[j4*4+0],
                                       acc[i][j4*4+1] + bsum[j4*4+1],
                                       acc[i][j4*4+2] + bsum[j4*4+2],
                                       acc[i][j4*4+3] + bsum[j4*4+3]);
                *(float4*)(yo + j4 * 4) = v;
            }
        }
    }
}

// ---------------- K2: histogram of dst ---------------------------------------
__global__ void hist_kernel(const int* __restrict__ ei) {
    int e = blockIdx.x * blockDim.x + threadIdx.x;
    if (e < EE) atomicAdd(&g_counts[ei[EE + e]], 1);
}

// ---------------- K3a: per-block exclusive scan ------------------------------
__global__ void scan_blocks_kernel() {
    __shared__ int wsum[16];
    int t = threadIdx.x, lane = t & 31, w = t >> 5;
    int idx = blockIdx.x * SCAN_BS + t;
    int v = (idx < NN) ? g_counts[idx] : 0;
    int s = v;
#pragma unroll
    for (int d = 1; d < 32; d <<= 1) {
        int u = __shfl_up_sync(0xFFFFFFFFu, s, d);
        if (lane >= d) s += u;
    }
    if (lane == 31) wsum[w] = s;
    __syncthreads();
    if (w == 0) {
        int ws = (lane < 16) ? wsum[lane] : 0;
#pragma unroll
        for (int d = 1; d < 16; d <<= 1) {
            int u = __shfl_up_sync(0xFFFFFFFFu, ws, d);
            if (lane >= d) ws += u;
        }
        if (lane < 16) wsum[lane] = ws;
    }
    __syncthreads();
    int excl = (w > 0 ? wsum[w - 1] : 0) + s - v;
    if (idx < NN) g_offsets[idx] = excl;
    if (t == SCAN_BS - 1) g_part[blockIdx.x] = wsum[15];
}

// ---------------- K3b: add block prefixes (scans the 98 partials inline) -----
__global__ void scan_add_kernel() {
    __shared__ int spart[128];
    int t = threadIdx.x;                       // 256 threads
    if (t < 128) spart[t] = (t < SCAN_NB) ? g_part[t] : 0;
    __syncthreads();
    for (int d = 1; d < 128; d <<= 1) {        // Hillis-Steele inclusive scan
        int v = (t < 128 && t >= d) ? spart[t - d] : 0;
        __syncthreads();
        if (t < 128) spart[t] += v;
        __syncthreads();
    }
    int i = blockIdx.x * 256 + t;
    if (i < NN) {
        int b = i / SCAN_BS;
        int o = g_offsets[i] + (b > 0 ? spart[b - 1] : 0);
        g_offsets[i] = o;
        g_cursor[i]  = o;
    }
}

// ---------------- K4: scatter edges into CSR order (2 edges/thread) ----------
__global__ void scatter_kernel(const int* __restrict__ ei, const float* __restrict__ ea) {
    int base = (blockIdx.x * blockDim.x + threadIdx.x) * 2;
#pragma unroll
    for (int u = 0; u < 2; u++) {
        int e = base + u;
        if (e < EE) {
            int d = ei[EE + e];
            int p = atomicAdd(&g_cursor[d], 1);
            g_sa_csr[p] = make_int2(ei[e], __float_as_int(ea[e]));
        }
    }
}

// ---------------- K5: fused logits + softmax + weighted segment-max ----------
// warp per dst node; 8 warps/block. Pass 1: 8 lanes/edge logits -> smem cache.
// Pass 2: 32-lane x float2, y rows L1-hot from pass 1.
__global__ void fused_kernel(const float* __restrict__ x, const float* __restrict__ We,
                             const float* __restrict__ att, float* __restrict__ out) {
    __shared__ float slog[8][CAP];
    int warp = threadIdx.x >> 5, lane = threadIdx.x & 31;
    int n = blockIdx.x * 8 + warp;
    if (n >= NN) return;

    int off = g_offsets[n];
    int k   = g_counts[n];
    int c0  = lane << 1;

    float2 xv = *(const float2*)(x + ((long)n << 6) + c0);
    float o0 = xv.x, o1 = xv.y;

    if (k > 0) {
        // ---- pass 1: logits (8 lanes per edge, 4 edges in flight) ----
        int g = lane >> 3, r = lane & 7;
        float4 we0 = ((const float4*)We)[r],  we1 = ((const float4*)We)[8 + r];
        float4 at0 = ((const float4*)att)[r], at1 = ((const float4*)att)[8 + r];
        for (int j0 = 0; j0 < k; j0 += 4) {
            int j = j0 + g;
            float v = 0.f;
            if (j < k) {
                int2 sa = g_sa_csr[off + j];
                float a = __int_as_float(sa.y);
                const float4* yr = (const float4*)(g_y + ((long)sa.x << 6));
                float4 y0 = yr[r], y1 = yr[8 + r];
                float m;
                m = y0.x + a * we0.x; v += fmaxf(m, 0.2f * m) * at0.x;
                m = y0.y + a * we0.y; v += fmaxf(m, 0.2f * m) * at0.y;
                m = y0.z + a * we0.z; v += fmaxf(m, 0.2f * m) * at0.z;
                m = y0.w + a * we0.w; v += fmaxf(m, 0.2f * m) * at0.w;
                m = y1.x + a * we1.x; v += fmaxf(m, 0.2f * m) * at1.x;
                m = y1.y + a * we1.y; v += fmaxf(m, 0.2f * m) * at1.y;
                m = y1.z + a * we1.z; v += fmaxf(m, 0.2f * m) * at1.z;
                m = y1.w + a * we1.w; v += fmaxf(m, 0.2f * m) * at1.w;
            }
            v += __shfl_xor_sync(0xFFFFFFFFu, v, 4);
            v += __shfl_xor_sync(0xFFFFFFFFu, v, 2);
            v += __shfl_xor_sync(0xFFFFFFFFu, v, 1);
            if (r == 0 && j < k) {
                if (j < CAP) slog[warp][j] = v;
                else         g_logit_ovf[off + j] = v;
            }
        }
        __syncwarp();

        // ---- softmax stats over cached logits ----
        const float BIG = -1e30f;
        float mloc = BIG, sloc = 0.f;
        for (int i = lane; i < k; i += 32) {
            float l = (i < CAP) ? slog[warp][i] : g_logit_ovf[off + i];
            float nm = fmaxf(mloc, l);
            sloc = sloc * __expf(mloc - nm) + __expf(l - nm);
            mloc = nm;
        }
#pragma unroll
        for (int d = 16; d; d >>= 1) {
            float mo = __shfl_xor_sync(0xFFFFFFFFu, mloc, d);
            float so = __shfl_xor_sync(0xFFFFFFFFu, sloc, d);
            float mn = fmaxf(mloc, mo);
            sloc = sloc * __expf(mloc - mn) + so * __expf(mo - mn);
            mloc = mn;
        }
        float rden = 1.f / (sloc + 1e-16f);
        float m = mloc;

        // ---- pass 2: weighted segment max (y rows L1-hot) ----
        float2 we = *(const float2*)(We + c0);
        float a0 = BIG, a1 = BIG;
        int j = 0;
        for (; j + 4 <= k && j + 4 <= CAP; j += 4) {
            int2  s0 = g_sa_csr[off + j + 0];
            int2  s1 = g_sa_csr[off + j + 1];
            int2  s2 = g_sa_csr[off + j + 2];
            int2  s3 = g_sa_csr[off + j + 3];
            float l0 = slog[warp][j + 0];
            float l1 = slog[warp][j + 1];
            float l2 = slog[warp][j + 2];
            float l3 = slog[warp][j + 3];
            float2 y0 = *(const float2*)(g_y + ((long)s0.x << 6) + c0);
            float2 y1 = *(const float2*)(g_y + ((long)s1.x << 6) + c0);
            float2 y2 = *(const float2*)(g_y + ((long)s2.x << 6) + c0);
            float2 y3 = *(const float2*)(g_y + ((long)s3.x << 6) + c0);
            float al0 = __expf(l0 - m) * rden, av0 = __int_as_float(s0.y);
            float al1 = __expf(l1 - m) * rden, av1 = __int_as_float(s1.y);
            float al2 = __expf(l2 - m) * rden, av2 = __int_as_float(s2.y);
            float al3 = __expf(l3 - m) * rden, av3 = __int_as_float(s3.y);
            a0 = fmaxf(a0, (y0.x + av0 * we.x) * al0);
            a1 = fmaxf(a1, (y0.y + av0 * we.y) * al0);
            a0 = fmaxf(a0, (y1.x + av1 * we.x) * al1);
            a1 = fmaxf(a1, (y1.y + av1 * we.y) * al1);
            a0 = fmaxf(a0, (y2.x + av2 * we.x) * al2);
            a1 = fmaxf(a1, (y2.y + av2 * we.y) * al2);
            a0 = fmaxf(a0, (y3.x + av3 * we.x) * al3);
            a1 = fmaxf(a1, (y3.y + av3 * we.y) * al3);
        }
        for (; j < k; j++) {
            int2  s  = g_sa_csr[off + j];
            float l  = (j < CAP) ? slog[warp][j] : g_logit_ovf[off + j];
            float av = __int_as_float(s.y);
            float alpha = __expf(l - m) * rden;
            float2 yv = *(const float2*)(g_y + ((long)s.x << 6) + c0);
            a0 = fmaxf(a0, (yv.x + av * we.x) * alpha);
            a1 = fmaxf(a1, (yv.y + av * we.y) * alpha);
        }
        o0 += a0;
        o1 += a1;
    }
    *(float2*)(out + ((long)n << 6) + c0) = make_float2(o0, o1);
}

// ---------------- launch ------------------------------------------------------
extern "C" void kernel_launch(void* const* d_in, const int* in_sizes, int n_in,
                              void* d_out, int out_size) {
    const float* x   = (const float*)d_in[0];
    const int*   ei  = (const int*)d_in[1];
    const float* ea  = (const float*)d_in[2];
    const float* Wm  = (const float*)d_in[3];
    const float* bm  = (const float*)d_in[4];
    const float* We  = (const float*)d_in[5];
    const float* be  = (const float*)d_in[6];
    const float* att = (const float*)d_in[7];
    float*       out = (float*)d_out;
    (void)in_sizes; (void)n_in; (void)out_size;

    gemm_kernel<<<(NN + 127) / 128, 128>>>(x, Wm, bm, be);   // also zeros counts
    hist_kernel<<<(EE + 255) / 256, 256>>>(ei);
    scan_blocks_kernel<<<SCAN_NB, SCAN_BS>>>();
    scan_add_kernel<<<(NN + 255) / 256, 256>>>();
    scatter_kernel<<<(EE / 2 + 255) / 256, 256>>>(ei, ea);
    fused_kernel<<<(NN + 7) / 8, 256>>>(x, We, att, out);
}

// round 9
// speedup vs baseline: 2.2057x; 1.0532x over previous
#include <cuda_runtime.h>

#define NN 50000
#define EE 800000
#define SCAN_BS 512
#define SCAN_NB ((NN + SCAN_BS - 1) / SCAN_BS)   // 98
#define NWARP 4          // warps per block in fused kernel
#define CAP_E 24         // per-warp msg-row cache (edges)
#define CAP_L 64         // per-warp logit cache

// ---------------- scratch (device globals; no allocations allowed) ----------
__device__ float g_y[NN * 64];        // y = x @ W_msg + (b_msg + b_edge)
__device__ int   g_counts[NN];
__device__ int   g_offsets[NN];
__device__ int   g_cursor[NN];
__device__ int   g_part[SCAN_NB];
__device__ int2  g_sa_csr[EE];        // per-CSR-slot: {src, edge_attr bits}
__device__ float g_logit_ovf[EE];     // overflow logits (k > CAP_L only)

// ---------------- K1: y = x @ W + (b_msg + b_edge); also zeros counts --------
__global__ void gemm_kernel(const float* __restrict__ x, const float* __restrict__ W,
                            const float* __restrict__ bm, const float* __restrict__ be) {
    __shared__ float sW[4096];
    __shared__ float sx[128 * 65];
    int t  = threadIdx.x;
    int r0 = blockIdx.x * 128;

    int gid = r0 + t;                       // folded init: zero dst counters
    if (gid < NN) g_counts[gid] = 0;

    for (int i = t; i < 1024; i += 128)
        ((float4*)sW)[i] = ((const float4*)W)[i];
    for (int i = t; i < 2048; i += 128) {
        int r = i >> 4, c4 = (i & 15) << 2;
        int gr = r0 + r;
        float4 v = (gr < NN) ? ((const float4*)x)[(gr << 4) + (c4 >> 2)]
                             : make_float4(0.f, 0.f, 0.f, 0.f);
        float* dst = sx + r * 65 + c4;
        dst[0] = v.x; dst[1] = v.y; dst[2] = v.z; dst[3] = v.w;
    }
    __syncthreads();

    int q  = t >> 2;
    int cg = (t & 3) << 4;
    float acc[4][16];
#pragma unroll
    for (int i = 0; i < 4; i++)
#pragma unroll
        for (int j = 0; j < 16; j++) acc[i][j] = 0.f;

#pragma unroll 4
    for (int k = 0; k < 64; k++) {
        const float* wr = sW + (k << 6) + cg;
        float4 w0 = *(const float4*)(wr);
        float4 w1 = *(const float4*)(wr + 4);
        float4 w2 = *(const float4*)(wr + 8);
        float4 w3 = *(const float4*)(wr + 12);
        float wv[16] = {w0.x,w0.y,w0.z,w0.w, w1.x,w1.y,w1.z,w1.w,
                        w2.x,w2.y,w2.z,w2.w, w3.x,w3.y,w3.z,w3.w};
#pragma unroll
        for (int i = 0; i < 4; i++) {
            float xv = sx[(q * 4 + i) * 65 + k];
#pragma unroll
            for (int j = 0; j < 16; j++) acc[i][j] += xv * wv[j];
        }
    }

    float bsum[16];
#pragma unroll
    for (int j = 0; j < 16; j++) bsum[j] = bm[cg + j] + be[cg + j];

#pragma unroll
    for (int i = 0; i < 4; i++) {
        int gr = r0 + q * 4 + i;
        if (gr < NN) {
            float* yo = g_y + ((long)gr << 6) + cg;
#pragma unroll
            for (int j4 = 0; j4 < 4; j4++) {
                float4 v = make_float4(acc[i][j4*4+0] + bsum[j4*4+0],
                                       acc[i][j4*4+1] + bsum[j4*4+1],
                                       acc[i][j4*4+2] + bsum[j4*4+2],
                                       acc[i][j4*4+3] + bsum[j4*4+3]);
                *(float4*)(yo + j4 * 4) = v;
            }
        }
    }
}

// ---------------- K2: histogram of dst ---------------------------------------
__global__ void hist_kernel(const int* __restrict__ ei) {
    int e = blockIdx.x * blockDim.x + threadIdx.x;
    if (e < EE) atomicAdd(&g_counts[ei[EE + e]], 1);
}

// ---------------- K3a: per-block exclusive scan ------------------------------
__global__ void scan_blocks_kernel() {
    __shared__ int wsum[16];
    int t = threadIdx.x, lane = t & 31, w = t >> 5;
    int idx = blockIdx.x * SCAN_BS + t;
    int v = (idx < NN) ? g_counts[idx] : 0;
    int s = v;
#pragma unroll
    for (int d = 1; d < 32; d <<= 1) {
        int u = __shfl_up_sync(0xFFFFFFFFu, s, d);
        if (lane >= d) s += u;
    }
    if (lane == 31) wsum[w] = s;
    __syncthreads();
    if (w == 0) {
        int ws = (lane < 16) ? wsum[lane] : 0;
#pragma unroll
        for (int d = 1; d < 16; d <<= 1) {
            int u = __shfl_up_sync(0xFFFFFFFFu, ws, d);
            if (lane >= d) ws += u;
        }
        if (lane < 16) wsum[lane] = ws;
    }
    __syncthreads();
    int excl = (w > 0 ? wsum[w - 1] : 0) + s - v;
    if (idx < NN) g_offsets[idx] = excl;
    if (t == SCAN_BS - 1) g_part[blockIdx.x] = wsum[15];
}

// ---------------- K3b: add block prefixes (scans the 98 partials inline) -----
__global__ void scan_add_kernel() {
    __shared__ int spart[128];
    int t = threadIdx.x;                       // 256 threads
    if (t < 128) spart[t] = (t < SCAN_NB) ? g_part[t] : 0;
    __syncthreads();
    for (int d = 1; d < 128; d <<= 1) {        // Hillis-Steele inclusive scan
        int v = (t < 128 && t >= d) ? spart[t - d] : 0;
        __syncthreads();
        if (t < 128) spart[t] += v;
        __syncthreads();
    }
    int i = blockIdx.x * 256 + t;
    if (i < NN) {
        int b = i / SCAN_BS;
        int o = g_offsets[i] + (b > 0 ? spart[b - 1] : 0);
        g_offsets[i] = o;
        g_cursor[i]  = o;
    }
}

// ---------------- K4: scatter edges into CSR order (2 edges/thread) ----------
__global__ void scatter_kernel(const int* __restrict__ ei, const float* __restrict__ ea) {
    int base = (blockIdx.x * blockDim.x + threadIdx.x) * 2;
#pragma unroll
    for (int u = 0; u < 2; u++) {
        int e = base + u;
        if (e < EE) {
            int d = ei[EE + e];
            int p = atomicAdd(&g_cursor[d], 1);
            g_sa_csr[p] = make_int2(ei[e], __float_as_int(ea[e]));
        }
    }
}

// ---------------- K5: fused logits + softmax + weighted segment-max ----------
// warp per dst node. Pass 1: 8 lanes/edge compute msg, cache msg rows in smem.
// Pass 2: alpha-weighted max straight from smem (no second gather).
__global__ void fused_kernel(const float* __restrict__ x, const float* __restrict__ We,
                             const float* __restrict__ att, float* __restrict__ out) {
    __shared__ float smsg[NWARP][CAP_E][64];   // 24 KB
    __shared__ float slog[NWARP][CAP_L];       // 1 KB
    int warp = threadIdx.x >> 5, lane = threadIdx.x & 31;
    int n = blockIdx.x * NWARP + warp;
    if (n >= NN) return;

    int off = g_offsets[n];
    int k   = g_counts[n];
    int c0  = lane << 1;

    float2 xv = *(const float2*)(x + ((long)n << 6) + c0);
    float o0 = xv.x, o1 = xv.y;

    if (k > 0) {
        // ---- pass 1: logits + msg-row cache (8 lanes/edge, 4 edges in flight) ----
        int g = lane >> 3, r = lane & 7;
        float4 we0 = ((const float4*)We)[r],  we1 = ((const float4*)We)[8 + r];
        float4 at0 = ((const float4*)att)[r], at1 = ((const float4*)att)[8 + r];
        for (int j0 = 0; j0 < k; j0 += 4) {
            int j = j0 + g;
            float v = 0.f;
            if (j < k) {
                int2 sa = g_sa_csr[off + j];
                float a = __int_as_float(sa.y);
                const float4* yr = (const float4*)(g_y + ((long)sa.x << 6));
                float4 y0 = yr[r], y1 = yr[8 + r];
                float4 m0, m1;
                m0.x = y0.x + a * we0.x; m0.y = y0.y + a * we0.y;
                m0.z = y0.z + a * we0.z; m0.w = y0.w + a * we0.w;
                m1.x = y1.x + a * we1.x; m1.y = y1.y + a * we1.y;
                m1.z = y1.z + a * we1.z; m1.w = y1.w + a * we1.w;
                v += fmaxf(m0.x, 0.2f * m0.x) * at0.x;
                v += fmaxf(m0.y, 0.2f * m0.y) * at0.y;
                v += fmaxf(m0.z, 0.2f * m0.z) * at0.z;
                v += fmaxf(m0.w, 0.2f * m0.w) * at0.w;
                v += fmaxf(m1.x, 0.2f * m1.x) * at1.x;
                v += fmaxf(m1.y, 0.2f * m1.y) * at1.y;
                v += fmaxf(m1.z, 0.2f * m1.z) * at1.z;
                v += fmaxf(m1.w, 0.2f * m1.w) * at1.w;
                if (j < CAP_E) {
                    *(float4*)&smsg[warp][j][r << 2]        = m0;
                    *(float4*)&smsg[warp][j][32 + (r << 2)] = m1;
                }
            }
            v += __shfl_xor_sync(0xFFFFFFFFu, v, 4);
            v += __shfl_xor_sync(0xFFFFFFFFu, v, 2);
            v += __shfl_xor_sync(0xFFFFFFFFu, v, 1);
            if (r == 0 && j < k) {
                if (j < CAP_L) slog[warp][j] = v;
                else           g_logit_ovf[off + j] = v;
            }
        }
        __syncwarp();

        // ---- softmax stats ----
        const float BIG = -1e30f;
        float mloc = BIG, sloc = 0.f;
        for (int i = lane; i < k; i += 32) {
            float l = (i < CAP_L) ? slog[warp][i] : g_logit_ovf[off + i];
            float nm = fmaxf(mloc, l);
            sloc = sloc * __expf(mloc - nm) + __expf(l - nm);
            mloc = nm;
        }
#pragma unroll
        for (int d = 16; d; d >>= 1) {
            float mo = __shfl_xor_sync(0xFFFFFFFFu, mloc, d);
            float so = __shfl_xor_sync(0xFFFFFFFFu, sloc, d);
            float mn = fmaxf(mloc, mo);
            sloc = sloc * __expf(mloc - mn) + so * __expf(mo - mn);
            mloc = mn;
        }
        float rden = 1.f / (sloc + 1e-16f);
        float m = mloc;

        // ---- pass 2: weighted max from smem ----
        float a0 = BIG, a1 = BIG;
        int jcap = (k < CAP_E) ? k : CAP_E;
        int j = 0;
        for (; j + 2 <= jcap; j += 2) {
            float2 v0 = *(const float2*)&smsg[warp][j    ][c0];
            float2 v1 = *(const float2*)&smsg[warp][j + 1][c0];
            float al0 = __expf(slog[warp][j    ] - m) * rden;
            float al1 = __expf(slog[warp][j + 1] - m) * rden;
            a0 = fmaxf(a0, v0.x * al0);
            a1 = fmaxf(a1, v0.y * al0);
            a0 = fmaxf(a0, v1.x * al1);
            a1 = fmaxf(a1, v1.y * al1);
        }
        for (; j < jcap; j++) {
            float2 v0 = *(const float2*)&smsg[warp][j][c0];
            float al = __expf(slog[warp][j] - m) * rden;
            a0 = fmaxf(a0, v0.x * al);
            a1 = fmaxf(a1, v0.y * al);
        }
        // overflow edges (k > CAP_E): re-gather from L2
        float2 we = *(const float2*)(We + c0);
        for (j = CAP_E; j < k; j++) {
            int2  s  = g_sa_csr[off + j];
            float l  = (j < CAP_L) ? slog[warp][j] : g_logit_ovf[off + j];
            float av = __int_as_float(s.y);
            float alpha = __expf(l - m) * rden;
            float2 yv = *(const float2*)(g_y + ((long)s.x << 6) + c0);
            a0 = fmaxf(a0, (yv.x + av * we.x) * alpha);
            a1 = fmaxf(a1, (yv.y + av * we.y) * alpha);
        }
        o0 += a0;
        o1 += a1;
    }
    *(float2*)(out + ((long)n << 6) + c0) = make_float2(o0, o1);
}

// ---------------- launch ------------------------------------------------------
extern "C" void kernel_launch(void* const* d_in, const int* in_sizes, int n_in,
                              void* d_out, int out_size) {
    const float* x   = (const float*)d_in[0];
    const int*   ei  = (const int*)d_in[1];
    const float* ea  = (const float*)d_in[2];
    const float* Wm  = (const float*)d_in[3];
    const float* bm  = (const float*)d_in[4];
    const float* We  = (const float*)d_in[5];
    const float* be  = (const float*)d_in[6];
    const float* att = (const float*)d_in[7];
    float*       out = (float*)d_out;
    (void)in_sizes; (void)n_in; (void)out_size;

    gemm_kernel<<<(NN + 127) / 128, 128>>>(x, Wm, bm, be);   // also zeros counts
    hist_kernel<<<(EE + 255) / 256, 256>>>(ei);
    scan_blocks_kernel<<<SCAN_NB, SCAN_BS>>>();
    scan_add_kernel<<<(NN + 255) / 256, 256>>>();
    scatter_kernel<<<(EE / 2 + 255) / 256, 256>>>(ei, ea);
    fused_kernel<<<(NN + NWARP - 1) / NWARP, NWARP * 32>>>(x, We, att, out);
}